// round 14
// baseline (speedup 1.0000x reference)
#include <cuda_runtime.h>
#include <cuda_fp16.h>

#define Nn 80000
#define Ee 1280000
#define Cc 64
#define NCELEM (Nn * Cc)
#define CAP 64   // bucket capacity (deg: mean 16, sigma 4 -> 12 sigma headroom)

// Scratch (static device arrays; no allocation anywhere)
__device__ __align__(256) __half g_h[NCELEM];     // h' = dis[row]*(x@W), fp16
__device__ __align__(256) __half g_xbuf[NCELEM];  // running x, fp16
__device__ float  g_dis[Nn];
__device__ int    g_cnt[Nn];
__device__ __align__(16) int2 g_bkt[(size_t)Nn * CAP];  // {src, w_bits}
__device__ double g_part[128];    // [0..63]=sum, [64..127]=sumsq
__device__ unsigned g_done;       // stats finalize counter (zero-init)
__device__ float  g_mv[2];        // mean, rstd of last LN

// ---------------------------------------------------------------------------
__device__ __forceinline__ unsigned smem_u32(const void* p) {
    return (unsigned)__cvta_generic_to_shared(p);
}
__device__ __forceinline__ void ldsm_x4(unsigned* r, unsigned addr) {
    asm volatile("ldmatrix.sync.aligned.m8n8.x4.shared.b16 {%0,%1,%2,%3}, [%4];\n"
                 : "=r"(r[0]), "=r"(r[1]), "=r"(r[2]), "=r"(r[3]) : "r"(addr));
}
__device__ __forceinline__ void ldsm_x2t(unsigned* r, unsigned addr) {
    asm volatile("ldmatrix.sync.aligned.m8n8.x2.trans.shared.b16 {%0,%1}, [%2];\n"
                 : "=r"(r[0]), "=r"(r[1]) : "r"(addr));
}
__device__ __forceinline__ void mma16816(float* c, const unsigned* a, const unsigned* b) {
    asm volatile(
        "mma.sync.aligned.m16n8k16.row.col.f32.f16.f16.f32 "
        "{%0,%1,%2,%3}, {%4,%5,%6,%7}, {%8,%9}, {%0,%1,%2,%3};\n"
        : "+f"(c[0]), "+f"(c[1]), "+f"(c[2]), "+f"(c[3])
        : "r"(a[0]), "r"(a[1]), "r"(a[2]), "r"(a[3]), "r"(b[0]), "r"(b[1]));
}

// ---------------------------------------------------------------------------
__global__ void zero_k() {
    int i = blockIdx.x * blockDim.x + threadIdx.x;
    if (i < Nn) g_cnt[i] = 0;
}

// Four edges per thread: 4 independent random atomic+store chains.
__global__ void fill_k(const int* __restrict__ src, const int* __restrict__ dst,
                       const float* __restrict__ ea) {
    int t = blockIdx.x * blockDim.x + threadIdx.x;  // grid exact Ee/4/256
    int e = t * 4;
    int4   d4 = *(const int4*)(dst + e);
    int4   s4 = *(const int4*)(src + e);
    float4 w4 = *(const float4*)(ea + e);
    int p0 = atomicAdd(&g_cnt[d4.x], 1);
    int p1 = atomicAdd(&g_cnt[d4.y], 1);
    int p2 = atomicAdd(&g_cnt[d4.z], 1);
    int p3 = atomicAdd(&g_cnt[d4.w], 1);
    if (p0 < CAP) g_bkt[((size_t)d4.x << 6) + p0] = make_int2(s4.x, __float_as_int(w4.x));
    if (p1 < CAP) g_bkt[((size_t)d4.y << 6) + p1] = make_int2(s4.y, __float_as_int(w4.y));
    if (p2 < CAP) g_bkt[((size_t)d4.z << 6) + p2] = make_int2(s4.z, __float_as_int(w4.z));
    if (p3 < CAP) g_bkt[((size_t)d4.w << 6) + p3] = make_int2(s4.w, __float_as_int(w4.w));
}

__global__ __launch_bounds__(256) void dis_k() {
    int lane = threadIdx.x & 31, wid = threadIdx.x >> 5;
    int node = blockIdx.x * 8 + wid;  // grid exact Nn/8
    int cnt = min(g_cnt[node], CAP);
    float s = 0.f;
    for (int i = lane; i < cnt; i += 32)
        s += __int_as_float(g_bkt[((size_t)node << 6) + i].y);
#pragma unroll
    for (int o = 16; o; o >>= 1) s += __shfl_xor_sync(0xffffffffu, s, o);
    if (lane == 0)
        g_dis[node] = s > 0.f ? rsqrtf(fmaxf(s, 1e-12f)) : 0.f;
}

// ---------------------------------------------------------------------------
// h' = dis .* (LN?(X) @ W), fp16 out, HMMA. 128 rows x 64 cols per block.
// X source: fp32 input (layer 0, no LN) or fp16 g_xbuf (layers 1,2 with LN).
__global__ __launch_bounds__(256) void gemm_k(const float* __restrict__ Xext,
                                              const float* __restrict__ W,
                                              const float* __restrict__ lnw,
                                              const float* __restrict__ lnb) {
    __shared__ __align__(16) __half Xh[128][72];  // 144B row stride
    __shared__ __align__(16) __half Wh[64][72];
    int tid  = threadIdx.x;
    int row0 = blockIdx.x * 128;

    if (blockIdx.x == 0 && tid < 128) g_part[tid] = 0.0;  // reset stats partials

    for (int i = tid; i < 1024; i += 256) {   // W: 64x64 floats
        float4 w4 = ((const float4*)W)[i];
        int r = i >> 4, c = (i & 15) * 4;
        __half2* p = (__half2*)&Wh[r][c];
        p[0] = __floats2half2_rn(w4.x, w4.y);
        p[1] = __floats2half2_rn(w4.z, w4.w);
    }
    if (Xext) {                               // fp32 input, no LN (layer 0)
        for (int i = tid; i < 2048; i += 256) {
            float4 x4 = ((const float4*)(Xext + (size_t)row0 * 64))[i];
            int r = i >> 4, c = (i & 15) * 4;
            __half2* p = (__half2*)&Xh[r][c];
            p[0] = __floats2half2_rn(x4.x, x4.y);
            p[1] = __floats2half2_rn(x4.z, x4.w);
        }
    } else {                                  // fp16 xbuf + lazy LN
        float m = g_mv[0], rs = g_mv[1];
        for (int i = tid; i < 1024; i += 256) {
            uint4 xv = ((const uint4*)g_xbuf)[row0 * 8 + i];
            int r = i >> 3, c = (i & 7) * 8;
            float2 f0 = __half22float2(*(__half2*)&xv.x);
            float2 f1 = __half22float2(*(__half2*)&xv.y);
            float2 f2 = __half22float2(*(__half2*)&xv.z);
            float2 f3 = __half22float2(*(__half2*)&xv.w);
            float4 wv0 = *(const float4*)(lnw + c), wv1 = *(const float4*)(lnw + c + 4);
            float4 bv0 = *(const float4*)(lnb + c), bv1 = *(const float4*)(lnb + c + 4);
            f0.x = (f0.x - m) * rs * wv0.x + bv0.x;
            f0.y = (f0.y - m) * rs * wv0.y + bv0.y;
            f1.x = (f1.x - m) * rs * wv0.z + bv0.z;
            f1.y = (f1.y - m) * rs * wv0.w + bv0.w;
            f2.x = (f2.x - m) * rs * wv1.x + bv1.x;
            f2.y = (f2.y - m) * rs * wv1.y + bv1.y;
            f3.x = (f3.x - m) * rs * wv1.z + bv1.z;
            f3.y = (f3.y - m) * rs * wv1.w + bv1.w;
            __half2* p = (__half2*)&Xh[r][c];
            p[0] = __floats2half2_rn(f0.x, f0.y);
            p[1] = __floats2half2_rn(f1.x, f1.y);
            p[2] = __floats2half2_rn(f2.x, f2.y);
            p[3] = __floats2half2_rn(f3.x, f3.y);
        }
    }
    __syncthreads();

    int wid = tid >> 5, lane = tid & 31;
    int m0 = wid * 16;                      // 8 warps x 16 rows = 128
    float cacc[8][4];
#pragma unroll
    for (int t = 0; t < 8; t++)
#pragma unroll
        for (int q = 0; q < 4; q++) cacc[t][q] = 0.f;

#pragma unroll
    for (int kc = 0; kc < 4; kc++) {
        int k0 = kc * 16;
        unsigned a[4];
        ldsm_x4(a, smem_u32(&Xh[m0 + (lane & 15)][k0 + ((lane >> 4) << 3)]));
#pragma unroll
        for (int nt = 0; nt < 8; nt++) {
            unsigned b[2];
            ldsm_x2t(b, smem_u32(&Wh[k0 + (lane & 15)][nt * 8]));
            mma16816(cacc[nt], a, b);
        }
    }
    __syncthreads();  // done reading Xh/Wh; reuse Xh as C staging

    int gid = lane >> 2, tig = lane & 3;
    int rl0 = m0 + gid;
    float d0 = g_dis[row0 + rl0], d1 = g_dis[row0 + rl0 + 8];
#pragma unroll
    for (int nt = 0; nt < 8; nt++) {
        int colb = nt * 8 + tig * 2;
        *(__half2*)&Xh[rl0][colb] =
            __floats2half2_rn(cacc[nt][0] * d0, cacc[nt][1] * d0);
        *(__half2*)&Xh[rl0 + 8][colb] =
            __floats2half2_rn(cacc[nt][2] * d1, cacc[nt][3] * d1);
    }
    __syncthreads();

    for (int j = tid; j < 1024; j += 256) { // 128 rows x 8 segs of 16B
        int row = j >> 3, seg = j & 7;
        uint4 v = *(const uint4*)&Xh[row][seg * 8];
        *(uint4*)(g_h + (size_t)(row0 + row) * 64 + seg * 8) = v;
    }
}

// ---------------------------------------------------------------------------
// Four nodes per warp, 8-lane quarters, uint4 per lane covers a 128B h-row.
// mode 0: relu -> fp16 xbuf + fused global stats (last block finalizes g_mv).
// mode 1: fp32 d_out.
__global__ __launch_bounds__(256) void gather_k(const float* __restrict__ xin,
                                                const float* __restrict__ b,
                                                const float* __restrict__ lnw,
                                                const float* __restrict__ lnb,
                                                float* __restrict__ outp,
                                                int mode, int out_size) {
    int lane = threadIdx.x & 31;
    int wid  = threadIdx.x >> 5;
    int qt   = lane >> 3;
    int ql   = lane & 7;
    unsigned qmask = 0xFFu << (qt * 8);
    int node = blockIdx.x * 32 + wid * 4 + qt;  // grid exact Nn/32
    int c8   = ql * 8;

    float acc[8];
#pragma unroll
    for (int k = 0; k < 8; k++) acc[k] = 0.f;

    int cnt = min(g_cnt[node], CAP);
    size_t base = (size_t)node << 6;

    for (int i = 0; i < cnt; i += 8) {
        int mm = min(cnt - i, 8);
        int2 ew = make_int2(0, 0);
        if (ql < mm) ew = g_bkt[base + i + ql];
        int j = 0;
        if (mm == 8) {
#pragma unroll
            for (; j < 8; j++) {
                int   s = __shfl_sync(qmask, ew.x, qt * 8 + j);
                float w = __int_as_float(__shfl_sync(qmask, ew.y, qt * 8 + j));
                uint4 hv = *(const uint4*)(g_h + (size_t)s * 64 + c8);
                float2 p0 = __half22float2(*(__half2*)&hv.x);
                float2 p1 = __half22float2(*(__half2*)&hv.y);
                float2 p2 = __half22float2(*(__half2*)&hv.z);
                float2 p3 = __half22float2(*(__half2*)&hv.w);
                acc[0] = fmaf(w, p0.x, acc[0]); acc[1] = fmaf(w, p0.y, acc[1]);
                acc[2] = fmaf(w, p1.x, acc[2]); acc[3] = fmaf(w, p1.y, acc[3]);
                acc[4] = fmaf(w, p2.x, acc[4]); acc[5] = fmaf(w, p2.y, acc[5]);
                acc[6] = fmaf(w, p3.x, acc[6]); acc[7] = fmaf(w, p3.y, acc[7]);
            }
        } else {
            for (; j < mm; j++) {
                int   s = __shfl_sync(qmask, ew.x, qt * 8 + j);
                float w = __int_as_float(__shfl_sync(qmask, ew.y, qt * 8 + j));
                uint4 hv = *(const uint4*)(g_h + (size_t)s * 64 + c8);
                float2 p0 = __half22float2(*(__half2*)&hv.x);
                float2 p1 = __half22float2(*(__half2*)&hv.y);
                float2 p2 = __half22float2(*(__half2*)&hv.z);
                float2 p3 = __half22float2(*(__half2*)&hv.w);
                acc[0] = fmaf(w, p0.x, acc[0]); acc[1] = fmaf(w, p0.y, acc[1]);
                acc[2] = fmaf(w, p1.x, acc[2]); acc[3] = fmaf(w, p1.y, acc[3]);
                acc[4] = fmaf(w, p2.x, acc[4]); acc[5] = fmaf(w, p2.y, acc[5]);
                acc[6] = fmaf(w, p3.x, acc[6]); acc[7] = fmaf(w, p3.y, acc[7]);
            }
        }
    }
    __syncwarp();  // reconverge quarters before full-warp ops

    float ds = g_dis[node];
    float xf[8];
    if (xin) {  // layer 0: fp32 input, no LN
        float4 a0 = *(const float4*)(xin + (size_t)node * 64 + c8);
        float4 a1 = *(const float4*)(xin + (size_t)node * 64 + c8 + 4);
        xf[0] = a0.x; xf[1] = a0.y; xf[2] = a0.z; xf[3] = a0.w;
        xf[4] = a1.x; xf[5] = a1.y; xf[6] = a1.z; xf[7] = a1.w;
    } else {    // fp16 xbuf
        uint4 xv = *(const uint4*)(g_xbuf + (size_t)node * 64 + c8);
        float2 f0 = __half22float2(*(__half2*)&xv.x);
        float2 f1 = __half22float2(*(__half2*)&xv.y);
        float2 f2 = __half22float2(*(__half2*)&xv.z);
        float2 f3 = __half22float2(*(__half2*)&xv.w);
        xf[0] = f0.x; xf[1] = f0.y; xf[2] = f1.x; xf[3] = f1.y;
        xf[4] = f2.x; xf[5] = f2.y; xf[6] = f3.x; xf[7] = f3.y;
    }
    if (lnw) {  // lazy LN of previous layer on residual path
        float m0 = g_mv[0], rs0 = g_mv[1];
#pragma unroll
        for (int k = 0; k < 8; k++)
            xf[k] = (xf[k] - m0) * rs0 * lnw[c8 + k] + lnb[c8 + k];
    }
    float v[8];
#pragma unroll
    for (int k = 0; k < 8; k++)
        v[k] = xf[k] + acc[k] * ds + b[c8 + k];

    if (mode == 0) {
        __shared__ float sh1[8], sh2[8];
        __shared__ bool  sdone;
        __shared__ double sAC[2];
#pragma unroll
        for (int k = 0; k < 8; k++) v[k] = fmaxf(v[k], 0.f);
        // round to fp16 storage; compute stats FROM the rounded values
        __half2 h0 = __floats2half2_rn(v[0], v[1]);
        __half2 h1 = __floats2half2_rn(v[2], v[3]);
        __half2 h2 = __floats2half2_rn(v[4], v[5]);
        __half2 h3 = __floats2half2_rn(v[6], v[7]);
        uint4 st;
        st.x = *(unsigned*)&h0; st.y = *(unsigned*)&h1;
        st.z = *(unsigned*)&h2; st.w = *(unsigned*)&h3;
        *(uint4*)(g_xbuf + (size_t)node * 64 + c8) = st;
        float2 r0 = __half22float2(h0), r1 = __half22float2(h1);
        float2 r2 = __half22float2(h2), r3 = __half22float2(h3);
        float s1 = ((r0.x + r0.y) + (r1.x + r1.y)) + ((r2.x + r2.y) + (r3.x + r3.y));
        float s2 = (r0.x * r0.x + r0.y * r0.y) + (r1.x * r1.x + r1.y * r1.y)
                 + (r2.x * r2.x + r2.y * r2.y) + (r3.x * r3.x + r3.y * r3.y);
#pragma unroll
        for (int o = 16; o; o >>= 1) {
            s1 += __shfl_xor_sync(0xffffffffu, s1, o);
            s2 += __shfl_xor_sync(0xffffffffu, s2, o);
        }
        if (lane == 0) { sh1[wid] = s1; sh2[wid] = s2; }
        if (threadIdx.x == 0) sdone = false;
        __syncthreads();
        if (threadIdx.x == 0) {
            float a = 0.f, c = 0.f;
#pragma unroll
            for (int q = 0; q < 8; q++) { a += sh1[q]; c += sh2[q]; }
            int slot = blockIdx.x & 63;
            atomicAdd(&g_part[slot], (double)a);
            atomicAdd(&g_part[64 + slot], (double)c);
            __threadfence();
            unsigned t = atomicAdd(&g_done, 1u);
            if (t == gridDim.x - 1) sdone = true;
        }
        __syncthreads();
        if (sdone) {  // last block: finalize mean/rstd for next layer
            int t = threadIdx.x;
            if (t < 64) {
                volatile double* vp = g_part;
                int base2 = (t >> 5) * 64;  // warp0: sum, warp1: sumsq
                int l = t & 31;
                double a = vp[base2 + l] + vp[base2 + l + 32];
#pragma unroll
                for (int o = 16; o; o >>= 1)
                    a += __shfl_xor_sync(0xffffffffu, a, o);
                if (l == 0) sAC[t >> 5] = a;
            }
            __syncthreads();
            if (t == 0) {
                double mean = sAC[0] / (double)NCELEM;
                double var  = sAC[1] / (double)NCELEM - mean * mean;
                if (var < 0.0) var = 0.0;
                g_mv[0] = (float)mean;
                g_mv[1] = 1.0f / ((float)sqrt(var) + 1e-5f);
                g_done = 0;
            }
        }
    } else {
        int o = node * 64 + c8;
        if (o + 7 < out_size) {
            *(float4*)(outp + o)     = make_float4(v[0], v[1], v[2], v[3]);
            *(float4*)(outp + o + 4) = make_float4(v[4], v[5], v[6], v[7]);
        }
    }
}

// Tuple tail, vectorized: edge_index (int->f32, exact) and edge_attr.
__global__ void tail_k(const int* __restrict__ ei, const float* __restrict__ ea,
                       float* __restrict__ out, int out_size) {
    int i = blockIdx.x * blockDim.x + threadIdx.x;  // over 3*Ee/4
    const int Q2 = 2 * Ee / 4, Q3 = 3 * Ee / 4;
    if (i < Q2) {
        int4 v = ((const int4*)ei)[i];
        int o = NCELEM + i * 4;
        if (o + 3 < out_size)
            ((float4*)out)[o >> 2] = make_float4((float)v.x, (float)v.y,
                                                 (float)v.z, (float)v.w);
    } else if (i < Q3) {
        int j = i - Q2;
        float4 f = ((const float4*)ea)[j];
        int o = NCELEM + 2 * Ee + j * 4;
        if (o + 3 < out_size) ((float4*)out)[o >> 2] = f;
    }
}

// ---------------------------------------------------------------------------
extern "C" void kernel_launch(void* const* d_in, const int* in_sizes, int n_in,
                              void* d_out, int out_size) {
    const float* x  = (const float*)d_in[0];
    const int*   ei = (const int*)d_in[1];
    const float* ea = (const float*)d_in[2];
    const float* Wl[3]  = {(const float*)d_in[3], (const float*)d_in[5], (const float*)d_in[7]};
    const float* bl[3]  = {(const float*)d_in[4], (const float*)d_in[6], (const float*)d_in[8]};
    const float* lnw[2] = {(const float*)d_in[9],  (const float*)d_in[11]};
    const float* lnb[2] = {(const float*)d_in[10], (const float*)d_in[12]};
    float* out = (float*)d_out;
    const int* src = ei;
    const int* dst = ei + Ee;

    zero_k<<<(Nn + 255) / 256, 256>>>();
    fill_k<<<Ee / 4 / 256, 256>>>(src, dst, ea);
    dis_k<<<Nn / 8, 256>>>();

    for (int l = 0; l < 3; l++) {
        const float* xin = (l == 0) ? x : nullptr;           // null -> g_xbuf
        const float* lw  = (l == 0) ? nullptr : lnw[l - 1];  // lazy LN params
        const float* lb  = (l == 0) ? nullptr : lnb[l - 1];
        gemm_k<<<Nn / 128, 256>>>(xin, Wl[l], lw, lb);       // resets partials
        if (l < 2) {
            gather_k<<<Nn / 32, 256>>>(xin, bl[l], lw, lb, nullptr, 0, 0);
        } else {
            gather_k<<<Nn / 32, 256>>>(xin, bl[l], lw, lb, out, 1, out_size);
        }
    }
    tail_k<<<(3 * Ee / 4 + 255) / 256, 256>>>(ei, ea, out, out_size);
}

// round 15
// speedup vs baseline: 1.1639x; 1.1639x over previous
#include <cuda_runtime.h>
#include <cuda_fp16.h>

#define Nn 80000
#define Ee 1280000
#define Cc 64
#define NCELEM (Nn * Cc)
#define CAP 64   // bucket capacity (deg: mean 16, sigma 4 -> 12 sigma headroom)

// Scratch (static device arrays; no allocation anywhere)
__device__ __align__(256) __half g_h[NCELEM];   // h' = dis[row] * (x @ W), fp16
__device__ __align__(256) float  g_xbuf[NCELEM];
__device__ float  g_dis[Nn];
__device__ int    g_cnt[Nn];
__device__ __align__(16) int2 g_bkt[(size_t)Nn * CAP];  // {src, w_bits}
__device__ double g_part[128];
__device__ float  g_mv[2];   // mean, rstd of last LN

// ---------------------------------------------------------------------------
__device__ __forceinline__ unsigned smem_u32(const void* p) {
    return (unsigned)__cvta_generic_to_shared(p);
}
__device__ __forceinline__ void ldsm_x4(unsigned* r, unsigned addr) {
    asm volatile("ldmatrix.sync.aligned.m8n8.x4.shared.b16 {%0,%1,%2,%3}, [%4];\n"
                 : "=r"(r[0]), "=r"(r[1]), "=r"(r[2]), "=r"(r[3]) : "r"(addr));
}
__device__ __forceinline__ void ldsm_x2t(unsigned* r, unsigned addr) {
    asm volatile("ldmatrix.sync.aligned.m8n8.x2.trans.shared.b16 {%0,%1}, [%2];\n"
                 : "=r"(r[0]), "=r"(r[1]) : "r"(addr));
}
__device__ __forceinline__ void mma16816(float* c, const unsigned* a, const unsigned* b) {
    asm volatile(
        "mma.sync.aligned.m16n8k16.row.col.f32.f16.f16.f32 "
        "{%0,%1,%2,%3}, {%4,%5,%6,%7}, {%8,%9}, {%0,%1,%2,%3};\n"
        : "+f"(c[0]), "+f"(c[1]), "+f"(c[2]), "+f"(c[3])
        : "r"(a[0]), "r"(a[1]), "r"(a[2]), "r"(a[3]), "r"(b[0]), "r"(b[1]));
}

// ---------------------------------------------------------------------------
__global__ void zero_k() {
    int i = blockIdx.x * blockDim.x + threadIdx.x;
    if (i < Nn) g_cnt[i] = 0;
}

// Eight edges per thread: 8 independent random atomic+store chains.
__global__ void fill_k(const int* __restrict__ src, const int* __restrict__ dst,
                       const float* __restrict__ ea) {
    int t = blockIdx.x * blockDim.x + threadIdx.x;  // grid exact Ee/8/256
    int e = t * 8;
#pragma unroll
    for (int u = 0; u < 8; u += 4) {
        int4   d4 = *(const int4*)(dst + e + u);
        int4   s4 = *(const int4*)(src + e + u);
        float4 w4 = *(const float4*)(ea + e + u);
        int p0 = atomicAdd(&g_cnt[d4.x], 1);
        int p1 = atomicAdd(&g_cnt[d4.y], 1);
        int p2 = atomicAdd(&g_cnt[d4.z], 1);
        int p3 = atomicAdd(&g_cnt[d4.w], 1);
        if (p0 < CAP) g_bkt[((size_t)d4.x << 6) + p0] = make_int2(s4.x, __float_as_int(w4.x));
        if (p1 < CAP) g_bkt[((size_t)d4.y << 6) + p1] = make_int2(s4.y, __float_as_int(w4.y));
        if (p2 < CAP) g_bkt[((size_t)d4.z << 6) + p2] = make_int2(s4.z, __float_as_int(w4.z));
        if (p3 < CAP) g_bkt[((size_t)d4.w << 6) + p3] = make_int2(s4.w, __float_as_int(w4.w));
    }
}

__global__ __launch_bounds__(256) void dis_k() {
    int lane = threadIdx.x & 31, wid = threadIdx.x >> 5;
    int node = blockIdx.x * 8 + wid;  // grid exact Nn/8
    int cnt = min(g_cnt[node], CAP);
    float s = 0.f;
    for (int i = lane; i < cnt; i += 32)
        s += __int_as_float(g_bkt[((size_t)node << 6) + i].y);
#pragma unroll
    for (int o = 16; o; o >>= 1) s += __shfl_xor_sync(0xffffffffu, s, o);
    if (lane == 0)
        g_dis[node] = s > 0.f ? rsqrtf(fmaxf(s, 1e-12f)) : 0.f;
}

// ---------------------------------------------------------------------------
// h' = dis .* (LN?(X) @ W), fp16 out, HMMA. 128 rows x 64 cols per block.
// Epilogue staged through smem for fully-coalesced uint4 global stores.
__global__ __launch_bounds__(256) void gemm_k(const float* __restrict__ Xext,
                                              const float* __restrict__ W,
                                              const float* __restrict__ lnw,
                                              const float* __restrict__ lnb) {
    __shared__ __align__(16) __half Xh[128][72];  // 144B row stride (16B-mult)
    __shared__ __align__(16) __half Wh[64][72];
    const float* X = Xext ? Xext : g_xbuf;
    int tid  = threadIdx.x;
    int row0 = blockIdx.x * 128;

    if (blockIdx.x == 0 && tid < 128) g_part[tid] = 0.0;  // reset stats partials

    float m = 0.f, rs = 1.f;
    if (lnw) { m = g_mv[0]; rs = g_mv[1]; }

    for (int i = tid; i < 1024; i += 256) {   // W: 64x64 floats
        float4 w4 = ((const float4*)W)[i];
        int r = i >> 4, c = (i & 15) * 4;
        __half2* p = (__half2*)&Wh[r][c];
        p[0] = __floats2half2_rn(w4.x, w4.y);
        p[1] = __floats2half2_rn(w4.z, w4.w);
    }
    for (int i = tid; i < 2048; i += 256) {   // X tile, lazy LN on load
        float4 x4 = ((const float4*)(X + (size_t)row0 * 64))[i];
        int r = i >> 4, c = (i & 15) * 4;
        if (lnw) {
            x4.x = (x4.x - m) * rs * lnw[c]     + lnb[c];
            x4.y = (x4.y - m) * rs * lnw[c + 1] + lnb[c + 1];
            x4.z = (x4.z - m) * rs * lnw[c + 2] + lnb[c + 2];
            x4.w = (x4.w - m) * rs * lnw[c + 3] + lnb[c + 3];
        }
        __half2* p = (__half2*)&Xh[r][c];
        p[0] = __floats2half2_rn(x4.x, x4.y);
        p[1] = __floats2half2_rn(x4.z, x4.w);
    }
    __syncthreads();

    int wid = tid >> 5, lane = tid & 31;
    int m0 = wid * 16;                      // 8 warps x 16 rows = 128
    float cacc[8][4];
#pragma unroll
    for (int t = 0; t < 8; t++)
#pragma unroll
        for (int q = 0; q < 4; q++) cacc[t][q] = 0.f;

#pragma unroll
    for (int kc = 0; kc < 4; kc++) {
        int k0 = kc * 16;
        unsigned a[4];
        ldsm_x4(a, smem_u32(&Xh[m0 + (lane & 15)][k0 + ((lane >> 4) << 3)]));
#pragma unroll
        for (int nt = 0; nt < 8; nt++) {
            unsigned b[2];
            ldsm_x2t(b, smem_u32(&Wh[k0 + (lane & 15)][nt * 8]));
            mma16816(cacc[nt], a, b);
        }
    }
    __syncthreads();  // done reading Xh/Wh; reuse Xh as C staging

    int gid = lane >> 2, tig = lane & 3;
    int rl0 = m0 + gid;                     // local rows rl0, rl0+8
    float d0 = g_dis[row0 + rl0], d1 = g_dis[row0 + rl0 + 8];
#pragma unroll
    for (int nt = 0; nt < 8; nt++) {
        int colb = nt * 8 + tig * 2;
        *(__half2*)&Xh[rl0][colb] =
            __floats2half2_rn(cacc[nt][0] * d0, cacc[nt][1] * d0);
        *(__half2*)&Xh[rl0 + 8][colb] =
            __floats2half2_rn(cacc[nt][2] * d1, cacc[nt][3] * d1);
    }
    __syncthreads();

    for (int j = tid; j < 1024; j += 256) { // 128 rows x 8 segs of 16B
        int row = j >> 3, seg = j & 7;
        uint4 v = *(const uint4*)&Xh[row][seg * 8];
        *(uint4*)(g_h + (size_t)(row0 + row) * 64 + seg * 8) = v;
    }
}

// ---------------------------------------------------------------------------
// Gather, smem-staged edges. Stage 1: each warp loads the full bucket lists of
// its 4 nodes with warp-wide coalesced loads. Stage 2: each 8-lane quarter
// walks its node's edges from smem (LDS broadcast, no shuffles, no masks) and
// gathers h rows (uint4 per lane = 128B row per quarter).
__global__ __launch_bounds__(256) void gather_k(const float* __restrict__ xin,
                                                const float* __restrict__ b,
                                                const float* __restrict__ lnw,
                                                const float* __restrict__ lnb,
                                                float* __restrict__ outp,
                                                int mode, int out_size) {
    __shared__ __align__(16) int2 sbkt[32][CAP];   // 16 KB
    int lane = threadIdx.x & 31;
    int wid  = threadIdx.x >> 5;
    int qt   = lane >> 3;
    int ql   = lane & 7;
    int nloc = wid * 4;                          // local node index base
    int node = blockIdx.x * 32 + nloc + qt;      // grid exact Nn/32
    int c8   = ql * 8;

    // Stage 1: warp-coalesced bucket staging for this warp's 4 nodes.
#pragma unroll
    for (int q4 = 0; q4 < 4; q4++) {
        int nd = blockIdx.x * 32 + nloc + q4;
        int c  = min(g_cnt[nd], CAP);
        if (lane < c)      sbkt[nloc + q4][lane]      = g_bkt[((size_t)nd << 6) + lane];
        if (lane + 32 < c) sbkt[nloc + q4][lane + 32] = g_bkt[((size_t)nd << 6) + lane + 32];
    }
    __syncwarp();

    // Stage 2: per-quarter edge walk from smem.
    float acc[8];
#pragma unroll
    for (int k = 0; k < 8; k++) acc[k] = 0.f;

    int cq = min(g_cnt[node], CAP);
    const int2* ebase = sbkt[nloc + qt];
    int j = 0;
    for (; j + 4 <= cq; j += 4) {
#pragma unroll
        for (int u = 0; u < 4; u++) {
            int2 e = ebase[j + u];
            float w = __int_as_float(e.y);
            uint4 hv = *(const uint4*)(g_h + (size_t)e.x * 64 + c8);
            float2 p0 = __half22float2(*(__half2*)&hv.x);
            float2 p1 = __half22float2(*(__half2*)&hv.y);
            float2 p2 = __half22float2(*(__half2*)&hv.z);
            float2 p3 = __half22float2(*(__half2*)&hv.w);
            acc[0] = fmaf(w, p0.x, acc[0]); acc[1] = fmaf(w, p0.y, acc[1]);
            acc[2] = fmaf(w, p1.x, acc[2]); acc[3] = fmaf(w, p1.y, acc[3]);
            acc[4] = fmaf(w, p2.x, acc[4]); acc[5] = fmaf(w, p2.y, acc[5]);
            acc[6] = fmaf(w, p3.x, acc[6]); acc[7] = fmaf(w, p3.y, acc[7]);
        }
    }
    for (; j < cq; j++) {
        int2 e = ebase[j];
        float w = __int_as_float(e.y);
        uint4 hv = *(const uint4*)(g_h + (size_t)e.x * 64 + c8);
        float2 p0 = __half22float2(*(__half2*)&hv.x);
        float2 p1 = __half22float2(*(__half2*)&hv.y);
        float2 p2 = __half22float2(*(__half2*)&hv.z);
        float2 p3 = __half22float2(*(__half2*)&hv.w);
        acc[0] = fmaf(w, p0.x, acc[0]); acc[1] = fmaf(w, p0.y, acc[1]);
        acc[2] = fmaf(w, p1.x, acc[2]); acc[3] = fmaf(w, p1.y, acc[3]);
        acc[4] = fmaf(w, p2.x, acc[4]); acc[5] = fmaf(w, p2.y, acc[5]);
        acc[6] = fmaf(w, p3.x, acc[6]); acc[7] = fmaf(w, p3.y, acc[7]);
    }
    __syncwarp();

    float ds = g_dis[node];
    const float* xi = xin ? xin : g_xbuf;
    float4 xv0 = *(const float4*)(xi + (size_t)node * 64 + c8);
    float4 xv1 = *(const float4*)(xi + (size_t)node * 64 + c8 + 4);
    if (lnw) {  // lazy LN of previous layer on residual path
        float m0 = g_mv[0], rs0 = g_mv[1];
        float4 w0 = *(const float4*)(lnw + c8), w1 = *(const float4*)(lnw + c8 + 4);
        float4 b0 = *(const float4*)(lnb + c8), b1 = *(const float4*)(lnb + c8 + 4);
        xv0.x = (xv0.x - m0) * rs0 * w0.x + b0.x;
        xv0.y = (xv0.y - m0) * rs0 * w0.y + b0.y;
        xv0.z = (xv0.z - m0) * rs0 * w0.z + b0.z;
        xv0.w = (xv0.w - m0) * rs0 * w0.w + b0.w;
        xv1.x = (xv1.x - m0) * rs0 * w1.x + b1.x;
        xv1.y = (xv1.y - m0) * rs0 * w1.y + b1.y;
        xv1.z = (xv1.z - m0) * rs0 * w1.z + b1.z;
        xv1.w = (xv1.w - m0) * rs0 * w1.w + b1.w;
    }
    float4 bb0 = *(const float4*)(b + c8), bb1 = *(const float4*)(b + c8 + 4);
    float4 v0 = make_float4(xv0.x + acc[0] * ds + bb0.x, xv0.y + acc[1] * ds + bb0.y,
                            xv0.z + acc[2] * ds + bb0.z, xv0.w + acc[3] * ds + bb0.w);
    float4 v1 = make_float4(xv1.x + acc[4] * ds + bb1.x, xv1.y + acc[5] * ds + bb1.y,
                            xv1.z + acc[6] * ds + bb1.z, xv1.w + acc[7] * ds + bb1.w);

    if (mode == 0) {
        v0.x = fmaxf(v0.x, 0.f); v0.y = fmaxf(v0.y, 0.f);
        v0.z = fmaxf(v0.z, 0.f); v0.w = fmaxf(v0.w, 0.f);
        v1.x = fmaxf(v1.x, 0.f); v1.y = fmaxf(v1.y, 0.f);
        v1.z = fmaxf(v1.z, 0.f); v1.w = fmaxf(v1.w, 0.f);
        *(float4*)(g_xbuf + (size_t)node * 64 + c8)     = v0;
        *(float4*)(g_xbuf + (size_t)node * 64 + c8 + 4) = v1;
        float s1 = ((v0.x + v0.y) + (v0.z + v0.w)) + ((v1.x + v1.y) + (v1.z + v1.w));
        float s2 = (v0.x * v0.x + v0.y * v0.y) + (v0.z * v0.z + v0.w * v0.w)
                 + (v1.x * v1.x + v1.y * v1.y) + (v1.z * v1.z + v1.w * v1.w);
#pragma unroll
        for (int o = 16; o; o >>= 1) {  // stats are global: full warp fine
            s1 += __shfl_xor_sync(0xffffffffu, s1, o);
            s2 += __shfl_xor_sync(0xffffffffu, s2, o);
        }
        __shared__ float sh1[8], sh2[8];
        if (lane == 0) { sh1[wid] = s1; sh2[wid] = s2; }
        __syncthreads();
        if (threadIdx.x == 0) {
            float a = 0.f, c = 0.f;
#pragma unroll
            for (int q = 0; q < 8; q++) { a += sh1[q]; c += sh2[q]; }
            int slot = blockIdx.x & 63;
            atomicAdd(&g_part[slot], (double)a);
            atomicAdd(&g_part[64 + slot], (double)c);
        }
    } else {
        int o = node * 64 + c8;
        if (o + 7 < out_size) {
            *(float4*)(outp + o)     = v0;
            *(float4*)(outp + o + 4) = v1;
        }
    }
}

// Reduce spread partials -> mean, rstd (for NEXT layer's lazy LN).
__global__ void stats_k() {
    int t = threadIdx.x;  // 64 threads
    double a = g_part[t], c = g_part[64 + t];
#pragma unroll
    for (int o = 16; o; o >>= 1) {
        a += __shfl_xor_sync(0xffffffffu, a, o);
        c += __shfl_xor_sync(0xffffffffu, c, o);
    }
    __shared__ double s[4];
    if ((t & 31) == 0) { s[(t >> 5) * 2] = a; s[(t >> 5) * 2 + 1] = c; }
    __syncthreads();
    if (t == 0) {
        double A = s[0] + s[2], C = s[1] + s[3];
        double mean = A / (double)NCELEM;
        double var  = C / (double)NCELEM - mean * mean;
        if (var < 0.0) var = 0.0;
        g_mv[0] = (float)mean;
        g_mv[1] = 1.0f / ((float)sqrt(var) + 1e-5f);
    }
}

// Tuple tail, vectorized: edge_index (int->f32, exact) and edge_attr.
__global__ void tail_k(const int* __restrict__ ei, const float* __restrict__ ea,
                       float* __restrict__ out, int out_size) {
    int i = blockIdx.x * blockDim.x + threadIdx.x;  // over 3*Ee/4
    const int Q2 = 2 * Ee / 4, Q3 = 3 * Ee / 4;
    if (i < Q2) {
        int4 v = ((const int4*)ei)[i];
        int o = NCELEM + i * 4;
        if (o + 3 < out_size)
            ((float4*)out)[o >> 2] = make_float4((float)v.x, (float)v.y,
                                                 (float)v.z, (float)v.w);
    } else if (i < Q3) {
        int j = i - Q2;
        float4 f = ((const float4*)ea)[j];
        int o = NCELEM + 2 * Ee + j * 4;
        if (o + 3 < out_size) ((float4*)out)[o >> 2] = f;
    }
}

// ---------------------------------------------------------------------------
extern "C" void kernel_launch(void* const* d_in, const int* in_sizes, int n_in,
                              void* d_out, int out_size) {
    const float* x  = (const float*)d_in[0];
    const int*   ei = (const int*)d_in[1];
    const float* ea = (const float*)d_in[2];
    const float* Wl[3]  = {(const float*)d_in[3], (const float*)d_in[5], (const float*)d_in[7]};
    const float* bl[3]  = {(const float*)d_in[4], (const float*)d_in[6], (const float*)d_in[8]};
    const float* lnw[2] = {(const float*)d_in[9],  (const float*)d_in[11]};
    const float* lnb[2] = {(const float*)d_in[10], (const float*)d_in[12]};
    float* out = (float*)d_out;
    const int* src = ei;
    const int* dst = ei + Ee;

    zero_k<<<(Nn + 255) / 256, 256>>>();
    fill_k<<<Ee / 8 / 256, 256>>>(src, dst, ea);
    dis_k<<<Nn / 8, 256>>>();

    for (int l = 0; l < 3; l++) {
        const float* xin = (l == 0) ? x : nullptr;           // null -> g_xbuf
        const float* lw  = (l == 0) ? nullptr : lnw[l - 1];  // lazy LN params
        const float* lb  = (l == 0) ? nullptr : lnb[l - 1];
        gemm_k<<<Nn / 128, 256>>>(xin, Wl[l], lw, lb);       // resets partials
        if (l < 2) {
            gather_k<<<Nn / 32, 256>>>(xin, bl[l], lw, lb, nullptr, 0, 0);
            stats_k<<<1, 64>>>();
        } else {
            gather_k<<<Nn / 32, 256>>>(xin, bl[l], lw, lb, out, 1, out_size);
        }
    }
    tail_k<<<(3 * Ee / 4 + 255) / 256, 256>>>(ei, ea, out, out_size);
}

// round 16
// speedup vs baseline: 1.1932x; 1.0252x over previous
#include <cuda_runtime.h>
#include <cuda_fp16.h>

#define Nn 80000
#define Ee 1280000
#define Cc 64
#define NCELEM (Nn * Cc)
#define CAP 64   // bucket capacity (deg: mean 16, sigma 4 -> 12 sigma headroom)

// Scratch (static device arrays; no allocation anywhere)
__device__ __align__(256) __half g_h[NCELEM];   // h' = dis[row] * (x @ W), fp16
__device__ __align__(256) float  g_xbuf[NCELEM];
__device__ float  g_dis[Nn];
__device__ int    g_cnt[Nn];
__device__ __align__(16) int2 g_bkt[(size_t)Nn * CAP];  // {src, w_bits}
__device__ double g_part[128];
__device__ float  g_mv[2];   // mean, rstd of last LN

// ---------------------------------------------------------------------------
__device__ __forceinline__ unsigned smem_u32(const void* p) {
    return (unsigned)__cvta_generic_to_shared(p);
}
__device__ __forceinline__ void ldsm_x4(unsigned* r, unsigned addr) {
    asm volatile("ldmatrix.sync.aligned.m8n8.x4.shared.b16 {%0,%1,%2,%3}, [%4];\n"
                 : "=r"(r[0]), "=r"(r[1]), "=r"(r[2]), "=r"(r[3]) : "r"(addr));
}
__device__ __forceinline__ void ldsm_x2t(unsigned* r, unsigned addr) {
    asm volatile("ldmatrix.sync.aligned.m8n8.x2.trans.shared.b16 {%0,%1}, [%2];\n"
                 : "=r"(r[0]), "=r"(r[1]) : "r"(addr));
}
__device__ __forceinline__ void mma16816(float* c, const unsigned* a, const unsigned* b) {
    asm volatile(
        "mma.sync.aligned.m16n8k16.row.col.f32.f16.f16.f32 "
        "{%0,%1,%2,%3}, {%4,%5,%6,%7}, {%8,%9}, {%0,%1,%2,%3};\n"
        : "+f"(c[0]), "+f"(c[1]), "+f"(c[2]), "+f"(c[3])
        : "r"(a[0]), "r"(a[1]), "r"(a[2]), "r"(a[3]), "r"(b[0]), "r"(b[1]));
}

// ---------------------------------------------------------------------------
// prep_k: first ZB blocks zero g_cnt; remaining blocks stream the tuple tail
// (edge_index -> f32, edge_attr). Runs first so the 8us tail overlaps zeroing
// and one launch disappears.
#define ZB ((Nn + 255) / 256)
__global__ void prep_k(const int* __restrict__ ei, const float* __restrict__ ea,
                       float* __restrict__ out, int out_size) {
    int blk = blockIdx.x;
    if (blk < ZB) {
        int i = blk * 256 + threadIdx.x;
        if (i < Nn) g_cnt[i] = 0;
        return;
    }
    int i = (blk - ZB) * 256 + threadIdx.x;  // over 3*Ee/4 vec4 items
    const int Q2 = 2 * Ee / 4, Q3 = 3 * Ee / 4;
    if (i < Q2) {
        int4 v = ((const int4*)ei)[i];
        int o = NCELEM + i * 4;
        if (o + 3 < out_size)
            ((float4*)out)[o >> 2] = make_float4((float)v.x, (float)v.y,
                                                 (float)v.z, (float)v.w);
    } else if (i < Q3) {
        int j = i - Q2;
        float4 f = ((const float4*)ea)[j];
        int o = NCELEM + 2 * Ee + j * 4;
        if (o + 3 < out_size) ((float4*)out)[o >> 2] = f;
    }
}

// Eight edges per thread: 8 independent random atomic+store chains.
__global__ void fill_k(const int* __restrict__ src, const int* __restrict__ dst,
                       const float* __restrict__ ea) {
    int t = blockIdx.x * blockDim.x + threadIdx.x;  // grid exact Ee/8/256
    int e = t * 8;
#pragma unroll
    for (int u = 0; u < 8; u += 4) {
        int4   d4 = *(const int4*)(dst + e + u);
        int4   s4 = *(const int4*)(src + e + u);
        float4 w4 = *(const float4*)(ea + e + u);
        int p0 = atomicAdd(&g_cnt[d4.x], 1);
        int p1 = atomicAdd(&g_cnt[d4.y], 1);
        int p2 = atomicAdd(&g_cnt[d4.z], 1);
        int p3 = atomicAdd(&g_cnt[d4.w], 1);
        if (p0 < CAP) g_bkt[((size_t)d4.x << 6) + p0] = make_int2(s4.x, __float_as_int(w4.x));
        if (p1 < CAP) g_bkt[((size_t)d4.y << 6) + p1] = make_int2(s4.y, __float_as_int(w4.y));
        if (p2 < CAP) g_bkt[((size_t)d4.z << 6) + p2] = make_int2(s4.z, __float_as_int(w4.z));
        if (p3 < CAP) g_bkt[((size_t)d4.w << 6) + p3] = make_int2(s4.w, __float_as_int(w4.w));
    }
}

__global__ __launch_bounds__(256) void dis_k() {
    int lane = threadIdx.x & 31, wid = threadIdx.x >> 5;
    int node = blockIdx.x * 8 + wid;  // grid exact Nn/8
    int cnt = min(g_cnt[node], CAP);
    float s = 0.f;
    for (int i = lane; i < cnt; i += 32)
        s += __int_as_float(g_bkt[((size_t)node << 6) + i].y);
#pragma unroll
    for (int o = 16; o; o >>= 1) s += __shfl_xor_sync(0xffffffffu, s, o);
    if (lane == 0)
        g_dis[node] = s > 0.f ? rsqrtf(fmaxf(s, 1e-12f)) : 0.f;
}

// ---------------------------------------------------------------------------
// h' = dis .* (LN?(X) @ W), fp16 out, HMMA. 128 rows x 64 cols per block.
// Epilogue staged through smem for fully-coalesced uint4 global stores.
__global__ __launch_bounds__(256) void gemm_k(const float* __restrict__ Xext,
                                              const float* __restrict__ W,
                                              const float* __restrict__ lnw,
                                              const float* __restrict__ lnb) {
    __shared__ __align__(16) __half Xh[128][72];  // 144B row stride (16B-mult)
    __shared__ __align__(16) __half Wh[64][72];
    const float* X = Xext ? Xext : g_xbuf;
    int tid  = threadIdx.x;
    int row0 = blockIdx.x * 128;

    if (blockIdx.x == 0 && tid < 128) g_part[tid] = 0.0;  // reset stats partials

    float m = 0.f, rs = 1.f;
    if (lnw) { m = g_mv[0]; rs = g_mv[1]; }

    for (int i = tid; i < 1024; i += 256) {   // W: 64x64 floats
        float4 w4 = ((const float4*)W)[i];
        int r = i >> 4, c = (i & 15) * 4;
        __half2* p = (__half2*)&Wh[r][c];
        p[0] = __floats2half2_rn(w4.x, w4.y);
        p[1] = __floats2half2_rn(w4.z, w4.w);
    }
    for (int i = tid; i < 2048; i += 256) {   // X tile, lazy LN on load
        float4 x4 = ((const float4*)(X + (size_t)row0 * 64))[i];
        int r = i >> 4, c = (i & 15) * 4;
        if (lnw) {
            x4.x = (x4.x - m) * rs * lnw[c]     + lnb[c];
            x4.y = (x4.y - m) * rs * lnw[c + 1] + lnb[c + 1];
            x4.z = (x4.z - m) * rs * lnw[c + 2] + lnb[c + 2];
            x4.w = (x4.w - m) * rs * lnw[c + 3] + lnb[c + 3];
        }
        __half2* p = (__half2*)&Xh[r][c];
        p[0] = __floats2half2_rn(x4.x, x4.y);
        p[1] = __floats2half2_rn(x4.z, x4.w);
    }
    __syncthreads();

    int wid = tid >> 5, lane = tid & 31;
    int m0 = wid * 16;                      // 8 warps x 16 rows = 128
    float cacc[8][4];
#pragma unroll
    for (int t = 0; t < 8; t++)
#pragma unroll
        for (int q = 0; q < 4; q++) cacc[t][q] = 0.f;

#pragma unroll
    for (int kc = 0; kc < 4; kc++) {
        int k0 = kc * 16;
        unsigned a[4];
        ldsm_x4(a, smem_u32(&Xh[m0 + (lane & 15)][k0 + ((lane >> 4) << 3)]));
#pragma unroll
        for (int nt = 0; nt < 8; nt++) {
            unsigned b[2];
            ldsm_x2t(b, smem_u32(&Wh[k0 + (lane & 15)][nt * 8]));
            mma16816(cacc[nt], a, b);
        }
    }
    __syncthreads();  // done reading Xh/Wh; reuse Xh as C staging

    int gid = lane >> 2, tig = lane & 3;
    int rl0 = m0 + gid;                     // local rows rl0, rl0+8
    float d0 = g_dis[row0 + rl0], d1 = g_dis[row0 + rl0 + 8];
#pragma unroll
    for (int nt = 0; nt < 8; nt++) {
        int colb = nt * 8 + tig * 2;
        *(__half2*)&Xh[rl0][colb] =
            __floats2half2_rn(cacc[nt][0] * d0, cacc[nt][1] * d0);
        *(__half2*)&Xh[rl0 + 8][colb] =
            __floats2half2_rn(cacc[nt][2] * d1, cacc[nt][3] * d1);
    }
    __syncthreads();

    for (int j = tid; j < 1024; j += 256) { // 128 rows x 8 segs of 16B
        int row = j >> 3, seg = j & 7;
        uint4 v = *(const uint4*)&Xh[row][seg * 8];
        *(uint4*)(g_h + (size_t)(row0 + row) * 64 + seg * 8) = v;
    }
}

// ---------------------------------------------------------------------------
// Gather, smem-staged edges. Stage 1: each warp loads the full bucket lists of
// its 4 nodes with warp-wide coalesced loads. Stage 2: each 8-lane quarter
// walks its node's edges from smem (LDS broadcast) and gathers h rows, 8
// LDG.128s in flight per lane.
__global__ __launch_bounds__(256) void gather_k(const float* __restrict__ xin,
                                                const float* __restrict__ b,
                                                const float* __restrict__ lnw,
                                                const float* __restrict__ lnb,
                                                float* __restrict__ outp,
                                                int mode, int out_size) {
    __shared__ __align__(16) int2 sbkt[32][CAP];   // 16 KB
    int lane = threadIdx.x & 31;
    int wid  = threadIdx.x >> 5;
    int qt   = lane >> 3;
    int ql   = lane & 7;
    int nloc = wid * 4;                          // local node index base
    int node = blockIdx.x * 32 + nloc + qt;      // grid exact Nn/32
    int c8   = ql * 8;

    // Stage 1: warp-coalesced bucket staging for this warp's 4 nodes.
#pragma unroll
    for (int q4 = 0; q4 < 4; q4++) {
        int nd = blockIdx.x * 32 + nloc + q4;
        int c  = min(g_cnt[nd], CAP);
        if (lane < c)      sbkt[nloc + q4][lane]      = g_bkt[((size_t)nd << 6) + lane];
        if (lane + 32 < c) sbkt[nloc + q4][lane + 32] = g_bkt[((size_t)nd << 6) + lane + 32];
    }
    __syncwarp();

    // Stage 2: per-quarter edge walk from smem, MLP=8.
    float acc[8];
#pragma unroll
    for (int k = 0; k < 8; k++) acc[k] = 0.f;

    int cq = min(g_cnt[node], CAP);
    const int2* ebase = sbkt[nloc + qt];
    int j = 0;
    for (; j + 8 <= cq; j += 8) {
        uint4 hv[8];
        float w[8];
#pragma unroll
        for (int u = 0; u < 8; u++) {
            int2 e = ebase[j + u];
            w[u] = __int_as_float(e.y);
            hv[u] = *(const uint4*)(g_h + (size_t)e.x * 64 + c8);
        }
#pragma unroll
        for (int u = 0; u < 8; u++) {
            float2 p0 = __half22float2(*(__half2*)&hv[u].x);
            float2 p1 = __half22float2(*(__half2*)&hv[u].y);
            float2 p2 = __half22float2(*(__half2*)&hv[u].z);
            float2 p3 = __half22float2(*(__half2*)&hv[u].w);
            acc[0] = fmaf(w[u], p0.x, acc[0]); acc[1] = fmaf(w[u], p0.y, acc[1]);
            acc[2] = fmaf(w[u], p1.x, acc[2]); acc[3] = fmaf(w[u], p1.y, acc[3]);
            acc[4] = fmaf(w[u], p2.x, acc[4]); acc[5] = fmaf(w[u], p2.y, acc[5]);
            acc[6] = fmaf(w[u], p3.x, acc[6]); acc[7] = fmaf(w[u], p3.y, acc[7]);
        }
    }
    for (; j < cq; j++) {
        int2 e = ebase[j];
        float w = __int_as_float(e.y);
        uint4 hv = *(const uint4*)(g_h + (size_t)e.x * 64 + c8);
        float2 p0 = __half22float2(*(__half2*)&hv.x);
        float2 p1 = __half22float2(*(__half2*)&hv.y);
        float2 p2 = __half22float2(*(__half2*)&hv.z);
        float2 p3 = __half22float2(*(__half2*)&hv.w);
        acc[0] = fmaf(w, p0.x, acc[0]); acc[1] = fmaf(w, p0.y, acc[1]);
        acc[2] = fmaf(w, p1.x, acc[2]); acc[3] = fmaf(w, p1.y, acc[3]);
        acc[4] = fmaf(w, p2.x, acc[4]); acc[5] = fmaf(w, p2.y, acc[5]);
        acc[6] = fmaf(w, p3.x, acc[6]); acc[7] = fmaf(w, p3.y, acc[7]);
    }
    __syncwarp();

    float ds = g_dis[node];
    const float* xi = xin ? xin : g_xbuf;
    float4 xv0 = *(const float4*)(xi + (size_t)node * 64 + c8);
    float4 xv1 = *(const float4*)(xi + (size_t)node * 64 + c8 + 4);
    if (lnw) {  // lazy LN of previous layer on residual path
        float m0 = g_mv[0], rs0 = g_mv[1];
        float4 w0 = *(const float4*)(lnw + c8), w1 = *(const float4*)(lnw + c8 + 4);
        float4 b0 = *(const float4*)(lnb + c8), b1 = *(const float4*)(lnb + c8 + 4);
        xv0.x = (xv0.x - m0) * rs0 * w0.x + b0.x;
        xv0.y = (xv0.y - m0) * rs0 * w0.y + b0.y;
        xv0.z = (xv0.z - m0) * rs0 * w0.z + b0.z;
        xv0.w = (xv0.w - m0) * rs0 * w0.w + b0.w;
        xv1.x = (xv1.x - m0) * rs0 * w1.x + b1.x;
        xv1.y = (xv1.y - m0) * rs0 * w1.y + b1.y;
        xv1.z = (xv1.z - m0) * rs0 * w1.z + b1.z;
        xv1.w = (xv1.w - m0) * rs0 * w1.w + b1.w;
    }
    float4 bb0 = *(const float4*)(b + c8), bb1 = *(const float4*)(b + c8 + 4);
    float4 v0 = make_float4(xv0.x + acc[0] * ds + bb0.x, xv0.y + acc[1] * ds + bb0.y,
                            xv0.z + acc[2] * ds + bb0.z, xv0.w + acc[3] * ds + bb0.w);
    float4 v1 = make_float4(xv1.x + acc[4] * ds + bb1.x, xv1.y + acc[5] * ds + bb1.y,
                            xv1.z + acc[6] * ds + bb1.z, xv1.w + acc[7] * ds + bb1.w);

    if (mode == 0) {
        v0.x = fmaxf(v0.x, 0.f); v0.y = fmaxf(v0.y, 0.f);
        v0.z = fmaxf(v0.z, 0.f); v0.w = fmaxf(v0.w, 0.f);
        v1.x = fmaxf(v1.x, 0.f); v1.y = fmaxf(v1.y, 0.f);
        v1.z = fmaxf(v1.z, 0.f); v1.w = fmaxf(v1.w, 0.f);
        *(float4*)(g_xbuf + (size_t)node * 64 + c8)     = v0;
        *(float4*)(g_xbuf + (size_t)node * 64 + c8 + 4) = v1;
        float s1 = ((v0.x + v0.y) + (v0.z + v0.w)) + ((v1.x + v1.y) + (v1.z + v1.w));
        float s2 = (v0.x * v0.x + v0.y * v0.y) + (v0.z * v0.z + v0.w * v0.w)
                 + (v1.x * v1.x + v1.y * v1.y) + (v1.z * v1.z + v1.w * v1.w);
#pragma unroll
        for (int o = 16; o; o >>= 1) {  // stats are global: full warp fine
            s1 += __shfl_xor_sync(0xffffffffu, s1, o);
            s2 += __shfl_xor_sync(0xffffffffu, s2, o);
        }
        __shared__ float sh1[8], sh2[8];
        if (lane == 0) { sh1[wid] = s1; sh2[wid] = s2; }
        __syncthreads();
        if (threadIdx.x == 0) {
            float a = 0.f, c = 0.f;
#pragma unroll
            for (int q = 0; q < 8; q++) { a += sh1[q]; c += sh2[q]; }
            int slot = blockIdx.x & 63;
            atomicAdd(&g_part[slot], (double)a);
            atomicAdd(&g_part[64 + slot], (double)c);
        }
    } else {
        int o = node * 64 + c8;
        if (o + 7 < out_size) {
            *(float4*)(outp + o)     = v0;
            *(float4*)(outp + o + 4) = v1;
        }
    }
}

// Reduce spread partials -> mean, rstd (for NEXT layer's lazy LN).
__global__ void stats_k() {
    int t = threadIdx.x;  // 64 threads
    double a = g_part[t], c = g_part[64 + t];
#pragma unroll
    for (int o = 16; o; o >>= 1) {
        a += __shfl_xor_sync(0xffffffffu, a, o);
        c += __shfl_xor_sync(0xffffffffu, c, o);
    }
    __shared__ double s[4];
    if ((t & 31) == 0) { s[(t >> 5) * 2] = a; s[(t >> 5) * 2 + 1] = c; }
    __syncthreads();
    if (t == 0) {
        double A = s[0] + s[2], C = s[1] + s[3];
        double mean = A / (double)NCELEM;
        double var  = C / (double)NCELEM - mean * mean;
        if (var < 0.0) var = 0.0;
        g_mv[0] = (float)mean;
        g_mv[1] = 1.0f / ((float)sqrt(var) + 1e-5f);
    }
}

// ---------------------------------------------------------------------------
extern "C" void kernel_launch(void* const* d_in, const int* in_sizes, int n_in,
                              void* d_out, int out_size) {
    const float* x  = (const float*)d_in[0];
    const int*   ei = (const int*)d_in[1];
    const float* ea = (const float*)d_in[2];
    const float* Wl[3]  = {(const float*)d_in[3], (const float*)d_in[5], (const float*)d_in[7]};
    const float* bl[3]  = {(const float*)d_in[4], (const float*)d_in[6], (const float*)d_in[8]};
    const float* lnw[2] = {(const float*)d_in[9],  (const float*)d_in[11]};
    const float* lnb[2] = {(const float*)d_in[10], (const float*)d_in[12]};
    float* out = (float*)d_out;
    const int* src = ei;
    const int* dst = ei + Ee;

    int tail_blocks = (3 * Ee / 4 + 255) / 256;
    prep_k<<<ZB + tail_blocks, 256>>>(ei, ea, out, out_size);  // zero cnt + tuple tail
    fill_k<<<Ee / 8 / 256, 256>>>(src, dst, ea);
    dis_k<<<Nn / 8, 256>>>();

    for (int l = 0; l < 3; l++) {
        const float* xin = (l == 0) ? x : nullptr;           // null -> g_xbuf
        const float* lw  = (l == 0) ? nullptr : lnw[l - 1];  // lazy LN params
        const float* lb  = (l == 0) ? nullptr : lnb[l - 1];
        gemm_k<<<Nn / 128, 256>>>(xin, Wl[l], lw, lb);       // resets partials
        if (l < 2) {
            gather_k<<<Nn / 32, 256>>>(xin, bl[l], lw, lb, nullptr, 0, 0);
            stats_k<<<1, 64>>>();
        } else {
            gather_k<<<Nn / 32, 256>>>(xin, bl[l], lw, lb, out, 1, out_size);
        }
    }
}